// round 6
// baseline (speedup 1.0000x reference)
#include <cuda_runtime.h>

// Fused GwcVolumeCostProcessor: out [1, 64, 48, 128, 240] f32
//   ch 0..39  : groupwise correlation (mean over 8 ch of ref_gwc * shift(tgt_gwc,d))
//   ch 40..51 : ref_concat * (w >= d)
//   ch 52..63 : shift(tgt_concat, d)

#define HH 128
#define WW 240
#define DD 48
#define NG 40
#define CPG 8
#define HW (HH * WW)
#define W4 60                    // float4s per row
#define PAD 48                   // left zero-pad for tgt window
#define TW (PAD + WW)            // 288 padded row
#define NQ (DD / 4)              // 12 disparity quads
#define GWC_BLOCKS (NG * HH)     // 5120
#define CAT_BLOCKS (24 * DD * 2) // 2304 : (c, d, h-half)
#define INTERLEAVE (CAT_BLOCKS * 3) // 6912

__global__ __launch_bounds__(64) void fused_kernel(
    const float* __restrict__ ref, const float* __restrict__ tgt,
    const float* __restrict__ refc, const float* __restrict__ tgtc,
    float* __restrict__ out)
{
    __shared__ float stgt[CPG][TW];

    const int bid0 = blockIdx.x;
    const int tid  = threadIdx.x;

    // interleave: every 3rd block (of the first 6912) is a concat block
    bool is_cat;
    int id;
    if (bid0 < INTERLEAVE) {
        int q = bid0 / 3;
        int r = bid0 - q * 3;
        if (r == 2) { is_cat = true;  id = q; }
        else        { is_cat = false; id = 2 * q + r; }
    } else {
        is_cat = false;
        id = 2 * (INTERLEAVE / 3) + (bid0 - INTERLEAVE);
    }

    if (!is_cat) {
        // ---------------- gwc: one block per (group, h-row) ----------------
        const int g = id >> 7;
        const int h = id & 127;

        const float* tgtp = tgt + ((size_t)g * CPG) * HW + (size_t)h * WW;

        // fill padded tgt rows: 8 channels x 72 float4 (first 12 = zeros)
        for (int i = tid; i < CPG * (TW / 4); i += 64) {
            int c = i / (TW / 4);
            int x = i - c * (TW / 4);
            float4 v;
            if (x < PAD / 4) v = make_float4(0.f, 0.f, 0.f, 0.f);
            else v = *(const float4*)(tgtp + (size_t)c * HW + (size_t)(x - PAD / 4) * 4);
            *(float4*)&stgt[c][x * 4] = v;
        }
        __syncthreads();

        if (tid >= W4) return;
        const int w4 = tid * 4;

        // ref channel values -> registers, pre-scaled by 1/8
        const float* refp = ref + ((size_t)g * CPG) * HW + (size_t)h * WW + w4;
        float4 r[CPG];
#pragma unroll
        for (int c = 0; c < CPG; c++) {
            float4 v = *(const float4*)(refp + (size_t)c * HW);
            v.x *= 0.125f; v.y *= 0.125f; v.z *= 0.125f; v.w *= 0.125f;
            r[c] = v;
        }

        // window state: win = aligned float4 at element PAD+w4-4*(q-1)
        const int base = (PAD / 4) + tid;  // float4 index at d=0
        float4 win[CPG];
#pragma unroll
        for (int c = 0; c < CPG; c++)
            win[c] = ((const float4*)stgt[c])[base];

        float* op = out + (((size_t)g * DD) * HH + h) * WW + w4;

#pragma unroll 2
        for (int q = 1; q <= NQ; q++) {
            // conflict-free aligned refill: next lower quad of the window
            float4 nxt[CPG];
#pragma unroll
            for (int c = 0; c < CPG; c++)
                nxt[c] = ((const float4*)stgt[c])[base - q];

            float4 a;
            // j=0 : window = win
            a = make_float4(0.f, 0.f, 0.f, 0.f);
#pragma unroll
            for (int c = 0; c < CPG; c++) {
                a.x += r[c].x * win[c].x; a.y += r[c].y * win[c].y;
                a.z += r[c].z * win[c].z; a.w += r[c].w * win[c].w;
            }
            *(float4*)op = a; op += HW;

            // j=1 : window = (nxt.w, win.x, win.y, win.z)
            a = make_float4(0.f, 0.f, 0.f, 0.f);
#pragma unroll
            for (int c = 0; c < CPG; c++) {
                a.x += r[c].x * nxt[c].w; a.y += r[c].y * win[c].x;
                a.z += r[c].z * win[c].y; a.w += r[c].w * win[c].z;
            }
            *(float4*)op = a; op += HW;

            // j=2 : window = (nxt.z, nxt.w, win.x, win.y)
            a = make_float4(0.f, 0.f, 0.f, 0.f);
#pragma unroll
            for (int c = 0; c < CPG; c++) {
                a.x += r[c].x * nxt[c].z; a.y += r[c].y * nxt[c].w;
                a.z += r[c].z * win[c].x; a.w += r[c].w * win[c].y;
            }
            *(float4*)op = a; op += HW;

            // j=3 : window = (nxt.y, nxt.z, nxt.w, win.x)
            a = make_float4(0.f, 0.f, 0.f, 0.f);
#pragma unroll
            for (int c = 0; c < CPG; c++) {
                a.x += r[c].x * nxt[c].y; a.y += r[c].y * nxt[c].z;
                a.z += r[c].z * nxt[c].w; a.w += r[c].w * win[c].x;
            }
            *(float4*)op = a; op += HW;

            // rotate window
#pragma unroll
            for (int c = 0; c < CPG; c++) win[c] = nxt[c];
        }
    } else {
        // ---------------- concat: one block per (c, d, h-half) ----------------
        const int c    = id / (DD * 2);
        const int rem  = id - c * (DD * 2);
        const int d    = rem >> 1;
        const int half = rem & 1;

        float* op = out + (size_t)(NG + c) * DD * HW + (size_t)d * HW
                        + (size_t)half * 64 * WW;

        if (c < 12) {
            const float* rp = refc + (size_t)c * HW + (size_t)half * 64 * WW;
            for (int i = tid; i < 64 * W4; i += 64) {
                int h  = i / W4;
                int w4 = (i - h * W4) * 4;
                float4 v = *(const float4*)(rp + h * WW + w4);
                if (w4 < d) {
                    if (w4 + 0 < d) v.x = 0.f;
                    if (w4 + 1 < d) v.y = 0.f;
                    if (w4 + 2 < d) v.z = 0.f;
                    if (w4 + 3 < d) v.w = 0.f;
                }
                *(float4*)(op + h * WW + w4) = v;
            }
        } else {
            const float* tp = tgtc + (size_t)(c - 12) * HW + (size_t)half * 64 * WW;
            for (int i = tid; i < 64 * W4; i += 64) {
                int h  = i / W4;
                int w4 = (i - h * W4) * 4;
                const float* row = tp + h * WW;
                float4 v;
                v.x = (w4 + 0 >= d) ? row[w4 + 0 - d] : 0.f;
                v.y = (w4 + 1 >= d) ? row[w4 + 1 - d] : 0.f;
                v.z = (w4 + 2 >= d) ? row[w4 + 2 - d] : 0.f;
                v.w = (w4 + 3 >= d) ? row[w4 + 3 - d] : 0.f;
                *(float4*)(op + h * WW + w4) = v;
            }
        }
    }
}

extern "C" void kernel_launch(void* const* d_in, const int* in_sizes, int n_in,
                              void* d_out, int out_size)
{
    const float* ref_gwc    = (const float*)d_in[0];
    const float* tgt_gwc    = (const float*)d_in[1];
    const float* ref_concat = (const float*)d_in[2];
    const float* tgt_concat = (const float*)d_in[3];
    float* out = (float*)d_out;

    fused_kernel<<<GWC_BLOCKS + CAT_BLOCKS, 64>>>(
        ref_gwc, tgt_gwc, ref_concat, tgt_concat, out);
}